// round 8
// baseline (speedup 1.0000x reference)
#include <cuda_runtime.h>
#include <math.h>

#define BATCH 32
#define NIN   1024
#define NC    20
#define DIM   64
#define CD    (NC*DIM)   // 1280
#define CIN   128

// ---------------- scratch (device globals: no allocations allowed) ----------
__device__ float g_uhat[(size_t)BATCH * NIN * CD];   // 167.8 MB
__device__ float g_bij[BATCH * NIN * NC];            // routing logits
__device__ float g_spart[BATCH * NC * DIM];          // partial weighted sums (zeroed by squash)
__device__ float g_wsum[BATCH * NC];                 // partial weight sums
__device__ float g_v[BATCH * NC * DIM];              // v per iteration
__device__ float g_vn2[BATCH * NC];                  // |v|^2 per (b,class)

// ---------------- packed f32x2 helpers --------------------------------------
__device__ __forceinline__ void ffma2(unsigned long long &d,
                                      unsigned long long a,
                                      unsigned long long b) {
    asm("fma.rn.f32x2 %0, %1, %2, %0;" : "+l"(d) : "l"(a), "l"(b));
}
__device__ __forceinline__ float2 upk(unsigned long long v) {
    float2 f;
    asm("mov.b64 {%0, %1}, %2;" : "=f"(f.x), "=f"(f.y) : "l"(v));
    return f;
}

// ---------------- Kernel 1: u_hat GEMM (double-buffered w prefetch) ---------
// grid = (CD/128 = 10, NIN), block = 256.
// Block: one n, all 32 b, 128 consecutive cd rows.
// Thread tile: 2 b x 8 cd. w streamed through two 8x16B register buffers
// (ping-pong): fma on buffer A while buffer B's next chunk is in flight.
__global__ __launch_bounds__(256, 2)
void k_gemm(const float* __restrict__ x, const float* __restrict__ w1) {
    __shared__ __align__(16) float xs[32 * 132];   // padded rows

    const int n      = blockIdx.y;
    const int cdBase = blockIdx.x * 128;
    const int t      = threadIdx.x;

    // stage x[:, n, :]  (32 x 128) into smem, coalesced
    for (int e = t; e < 32 * 128; e += 256) {
        int bb = e >> 7, i = e & 127;
        xs[bb * 132 + i] = x[((size_t)bb * NIN + n) * CIN + i];
    }
    __syncthreads();

    const int bh = t & 15;         // b pair: b = bh*2 + {0,1}
    const int cg = t >> 4;         // cd = cdBase + cg*8 + r
    const float* wp = w1 + ((size_t)n * CD + cdBase + cg * 8) * CIN;

    unsigned long long acc[2][8];
    #pragma unroll
    for (int bi = 0; bi < 2; bi++)
        #pragma unroll
        for (int r = 0; r < 8; r++) acc[bi][r] = 0ull;

    // preload both buffers: wa = i[0..3], wb = i[4..7]
    ulonglong2 wa[8], wb[8];
    #pragma unroll
    for (int r = 0; r < 8; r++) wa[r] = *(const ulonglong2*)(wp + r * CIN);
    #pragma unroll
    for (int r = 0; r < 8; r++) wb[r] = *(const ulonglong2*)(wp + r * CIN + 4);

    const float* xr0 = xs + (bh * 2 + 0) * 132;
    const float* xr1 = xs + (bh * 2 + 1) * 132;

    #pragma unroll
    for (int i0 = 0; i0 < CIN; i0 += 8) {
        // ---- phase A: consume wa (i0..i0+3) ----
        ulonglong2 xa0 = *(const ulonglong2*)(xr0 + i0);
        ulonglong2 xa1 = *(const ulonglong2*)(xr1 + i0);
        #pragma unroll
        for (int r = 0; r < 8; r++) {
            ffma2(acc[0][r], xa0.x, wa[r].x);
            ffma2(acc[0][r], xa0.y, wa[r].y);
            ffma2(acc[1][r], xa1.x, wa[r].x);
            ffma2(acc[1][r], xa1.y, wa[r].y);
        }
        // prefetch wa for i0+8 (clamped re-read on last phase: L1-hot, harmless)
        {
            int ip = i0 + 8; if (ip > 120) ip = 120;
            const float* pA = wp + ip;
            #pragma unroll
            for (int r = 0; r < 8; r++) wa[r] = *(const ulonglong2*)(pA + r * CIN);
        }
        // ---- phase B: consume wb (i0+4..i0+7) ----
        ulonglong2 xb0 = *(const ulonglong2*)(xr0 + i0 + 4);
        ulonglong2 xb1 = *(const ulonglong2*)(xr1 + i0 + 4);
        #pragma unroll
        for (int r = 0; r < 8; r++) {
            ffma2(acc[0][r], xb0.x, wb[r].x);
            ffma2(acc[0][r], xb0.y, wb[r].y);
            ffma2(acc[1][r], xb1.x, wb[r].x);
            ffma2(acc[1][r], xb1.y, wb[r].y);
        }
        // prefetch wb for i0+12
        {
            int ip = i0 + 12; if (ip > 124) ip = 124;
            const float* pB = wp + ip;
            #pragma unroll
            for (int r = 0; r < 8; r++) wb[r] = *(const ulonglong2*)(pB + r * CIN);
        }
    }

    // epilogue: horizontal add of packed pairs, vectorized store
    #pragma unroll
    for (int bi = 0; bi < 2; bi++) {
        const int b = bh * 2 + bi;
        float o[8];
        #pragma unroll
        for (int r = 0; r < 8; r++) {
            float2 f = upk(acc[bi][r]);
            o[r] = f.x + f.y;
        }
        float* op = g_uhat + ((size_t)b * NIN + n) * CD + cdBase + cg * 8;
        *(float4*)(op)     = make_float4(o[0], o[1], o[2], o[3]);
        *(float4*)(op + 4) = make_float4(o[4], o[5], o[6], o[7]);
    }
}

// ---------------- Kernel 1b: iteration-0 weighted sum -----------------------
// With b_ij = 0, c collapses to exactly 1/1024 for every (n, class), so
// s0[b,c,d] = sum_n u_hat / 1024. Pure streaming reduction, no softmax pass.
// spart accumulates sum_n u_hat (c_raw = 1 semantics), wsum = 1024.
// grid = (CD/256 = 5, BATCH, 8 n-segments), block = 256.
__global__ __launch_bounds__(256)
void k_sum0() {
    const int cd = blockIdx.x * 256 + threadIdx.x;
    const int b  = blockIdx.y;
    const int n0 = blockIdx.z * 128;

    const float* p = g_uhat + ((size_t)b * NIN + n0) * CD + cd;
    float s0 = 0.f, s1 = 0.f, s2 = 0.f, s3 = 0.f;
    #pragma unroll 4
    for (int k = 0; k < 128; k += 4) {
        s0 += p[(size_t)(k + 0) * CD];
        s1 += p[(size_t)(k + 1) * CD];
        s2 += p[(size_t)(k + 2) * CD];
        s3 += p[(size_t)(k + 3) * CD];
    }
    atomicAdd(&g_spart[b * CD + cd], (s0 + s1) + (s2 + s3));

    if (blockIdx.x == 0 && blockIdx.z == 0 && threadIdx.x < NC)
        g_wsum[b * NC + threadIdx.x] = 1024.0f;
}

// ---------------- Kernel 2: fused routing pass (iters 1,2) -------------------
__global__ __launch_bounds__(256)
void k_route(int iter) {
    __shared__ float v_s[CD];
    __shared__ float vn2_s[NC];
    __shared__ float sbuf[8][CD];
    __shared__ float wbuf[8][NC];

    const int b  = blockIdx.y;
    const int n0 = blockIdx.x * 32;
    const int t    = threadIdx.x;
    const int w    = t >> 5;
    const int lane = t & 31;

    for (int e = t; e < CD; e += 256) v_s[e] = g_v[b * CD + e];
    if (t < NC) vn2_s[t] = g_vn2[b * NC + t];
    __syncthreads();

    float2 sacc[NC];
    #pragma unroll
    for (int j = 0; j < NC; j++) sacc[j] = make_float2(0.f, 0.f);
    float cwacc = 0.f;

    for (int k = 0; k < 4; k++) {
        const int n = n0 + k * 8 + w;
        const float* up = g_uhat + ((size_t)b * NIN + n) * CD;

        float2 ur[NC];
        float myun2 = 0.f, mydot = 0.f;

        #pragma unroll
        for (int j = 0; j < NC; j++) {
            float2 u2 = *(const float2*)(up + j * DIM + 2 * lane);
            ur[j] = u2;
            float2 v2 = *(const float2*)(v_s + j * DIM + 2 * lane);
            float p = u2.x * u2.x + u2.y * u2.y;
            float q = u2.x * v2.x + u2.y * v2.y;
            #pragma unroll
            for (int off = 16; off > 0; off >>= 1) {
                p += __shfl_xor_sync(0xffffffffu, p, off);
                q += __shfl_xor_sync(0xffffffffu, q, off);
            }
            if (lane == j) { myun2 = p; mydot = q; }
        }

        float bnew = -3.0e38f;
        if (lane < NC) {
            float un2 = myun2;
            float a   = sqrtf(un2) / (0.5f + un2);          // squash scale of u_hat
            float dd  = 1.0f - (a * a * un2 - 2.0f * a * mydot + vn2_s[lane]);
            if (iter == 1) {
                bnew = dd;                                    // b was 0
                g_bij[(b * NIN + n) * NC + lane] = dd;
            } else {
                bnew = g_bij[(b * NIN + n) * NC + lane] + dd; // last iter: no store needed
            }
        }
        float m = bnew;
        #pragma unroll
        for (int off = 16; off > 0; off >>= 1)
            m = fmaxf(m, __shfl_xor_sync(0xffffffffu, m, off));
        float e = (lane < NC) ? __expf(bnew - m) : 0.0f;
        float ssum = e;
        #pragma unroll
        for (int off = 16; off > 0; off >>= 1)
            ssum += __shfl_xor_sync(0xffffffffu, ssum, off);
        float craw = e / ssum;

        // accumulate weighted sums (u_hat reused from registers)
        #pragma unroll
        for (int j = 0; j < NC; j++) {
            float cj = __shfl_sync(0xffffffffu, craw, j);
            sacc[j].x += cj * ur[j].x;
            sacc[j].y += cj * ur[j].y;
        }
        if (lane < NC) cwacc += craw;
    }

    // stage per-warp partials, block-reduce, one atomic per element per block
    #pragma unroll
    for (int j = 0; j < NC; j++)
        *(float2*)&sbuf[w][j * DIM + 2 * lane] = sacc[j];
    if (lane < NC) wbuf[w][lane] = cwacc;
    __syncthreads();

    for (int e = t; e < CD; e += 256) {
        float s = 0.f;
        #pragma unroll
        for (int ww = 0; ww < 8; ww++) s += sbuf[ww][e];
        atomicAdd(&g_spart[b * CD + e], s);
    }
    if (t < NC) {
        float s = 0.f;
        #pragma unroll
        for (int ww = 0; ww < 8; ww++) s += wbuf[ww][t];
        atomicAdd(&g_wsum[b * NC + t], s);
    }
}

// ---------------- Kernel 3: squash + (final) output --------------------------
__global__ __launch_bounds__(64)
void k_squash(int final_iter, float* __restrict__ out) {
    const int bj = blockIdx.x;          // b*NC + j
    const int d  = threadIdx.x;
    const int lane = d & 31, wp = d >> 5;

    float sv = g_spart[bj * DIM + d];
    float ws = g_wsum[bj];
    float s  = sv / ws;

    float p = s * s;
    #pragma unroll
    for (int off = 16; off > 0; off >>= 1)
        p += __shfl_xor_sync(0xffffffffu, p, off);
    __shared__ float red[2];
    if (lane == 0) red[wp] = p;
    __syncthreads();
    float s2 = red[0] + red[1];

    float sc = sqrtf(s2) / (0.5f + s2);
    float v  = sc * s;

    g_v[bj * DIM + d] = v;
    if (d == 0) g_vn2[bj] = sc * sc * s2;

    // reset partials so next iteration / next graph replay starts clean
    g_spart[bj * DIM + d] = 0.0f;
    if (d == 0) g_wsum[bj] = 0.0f;

    if (final_iter) {
        out[bj * DIM + d] = v;                                  // poses [B,C,D,1] flattened
        if (d == 0)
            out[BATCH * NC * DIM + bj] = sqrtf(sc * sc * s2);   // activations [B,C,1]
    }
}

// ---------------- launch -----------------------------------------------------
extern "C" void kernel_launch(void* const* d_in, const int* in_sizes, int n_in,
                              void* d_out, int out_size) {
    const float* x  = (const float*)d_in[0];
    const float* w1 = (const float*)d_in[1];
    if (n_in >= 2 && in_sizes[0] > in_sizes[1]) {   // defensive: x is the smaller input
        x  = (const float*)d_in[1];
        w1 = (const float*)d_in[0];
    }
    float* out = (float*)d_out;

    k_gemm<<<dim3(CD / 128, NIN), 256>>>(x, w1);

    k_sum0<<<dim3(CD / 256, BATCH, 8), 256>>>();
    k_squash<<<BATCH * NC, 64>>>(0, out);

    k_route<<<dim3(NIN / 32, BATCH), 256>>>(1);
    k_squash<<<BATCH * NC, 64>>>(0, out);

    k_route<<<dim3(NIN / 32, BATCH), 256>>>(2);
    k_squash<<<BATCH * NC, 64>>>(1, out);
}

// round 9
// speedup vs baseline: 1.2239x; 1.2239x over previous
#include <cuda_runtime.h>
#include <math.h>
#include <stdint.h>

#define BATCH 32
#define NIN   1024
#define NC    20
#define DIM   64
#define CD    (NC*DIM)   // 1280
#define CIN   128

// ---------------- scratch (device globals: no allocations allowed) ----------
__device__ float g_uhat[(size_t)BATCH * NIN * CD];   // 167.8 MB
__device__ float g_bij[BATCH * NIN * NC];            // routing logits
__device__ float g_spart[BATCH * NC * DIM];          // partial weighted sums (zeroed by squash)
__device__ float g_wsum[BATCH * NC];                 // partial weight sums
__device__ float g_v[BATCH * NC * DIM];              // v per iteration
__device__ float g_vn2[BATCH * NC];                  // |v|^2 per (b,class)

// ---------------- packed f32x2 helpers --------------------------------------
__device__ __forceinline__ void ffma2(unsigned long long &d,
                                      unsigned long long a,
                                      unsigned long long b) {
    asm("fma.rn.f32x2 %0, %1, %2, %0;" : "+l"(d) : "l"(a), "l"(b));
}
__device__ __forceinline__ float2 upk(unsigned long long v) {
    float2 f;
    asm("mov.b64 {%0, %1}, %2;" : "=f"(f.x), "=f"(f.y) : "l"(v));
    return f;
}
__device__ __forceinline__ void cp16(uint32_t dst, const float* src) {
    asm volatile("cp.async.cg.shared.global [%0], [%1], 16;\n"
                 :: "r"(dst), "l"(src));
}
#define CP_COMMIT() asm volatile("cp.async.commit_group;\n" ::: "memory")
#define CP_WAIT1()  asm volatile("cp.async.wait_group 1;\n" ::: "memory")

// ---------------- Kernel 1: u_hat GEMM (cp.async warp-private pipeline) -----
// grid = (CD/256 = 5, NIN), block = 256 (8 warps).
// Block: one n, all 32 b, 256 consecutive cd rows. Warp w owns rows
// [w*32, w*32+32). Thread tile: 4 b x 8 cd (bg = t&7, cg = t>>3).
// w streamed via cp.async.cg into a 3-stage, 1KB/stage warp-private smem ring.
// Slot swizzle phys(s) = s ^ (s>>4) makes the 4 distinct cg-row LDS.128 reads
// per (r,q) land on distinct bank quads (conflict-free); the 8 bg lanes
// broadcast-share each address.
__global__ __launch_bounds__(256, 2)
void k_gemm(const float* __restrict__ x, const float* __restrict__ w1) {
    __shared__ __align__(16) float xs[32 * 132];        // padded x tile
    __shared__ __align__(16) float wsm[8 * 3 * 256];    // 8 warps x 3 stages x 1KB

    const int n      = blockIdx.y;
    const int cdBase = blockIdx.x * 256;
    const int t      = threadIdx.x;
    const int w      = t >> 5;
    const int lane   = t & 31;

    // stage x[:, n, :]  (32 x 128) into smem, coalesced
    for (int e = t; e < 32 * 128; e += 256) {
        int bb = e >> 7, i = e & 127;
        xs[bb * 132 + i] = x[((size_t)bb * NIN + n) * CIN + i];
    }
    __syncthreads();

    // ---- producer-side mapping: lane handles w row cd = cdBase + w*32 + lane,
    //      two 16B pieces per chunk (i-quads q=0,1), slots s = 2*lane, 2*lane+1.
    const float* wrow = w1 + ((size_t)n * CD + cdBase + w * 32 + lane) * CIN;
    uint32_t wb = (uint32_t)__cvta_generic_to_shared(&wsm[w * 3 * 256]);
    const uint32_t d0 = wb + (uint32_t)(((2 * lane)     ^ (lane >> 3)) << 4);
    const uint32_t d1 = wb + (uint32_t)(((2 * lane + 1) ^ (lane >> 3)) << 4);

    // prologue: chunks 0,1 in flight
    {
        cp16(d0,        wrow + 0);  cp16(d1,        wrow + 4);  CP_COMMIT();
        cp16(d0 + 1024, wrow + 8);  cp16(d1 + 1024, wrow + 12); CP_COMMIT();
    }

    const int bg = t & 7;
    const int cg = t >> 3;
    const int cq = cg & 3;

    unsigned long long acc[4][8];
    #pragma unroll
    for (int bi = 0; bi < 4; bi++)
        #pragma unroll
        for (int r = 0; r < 8; r++) acc[bi][r] = 0ull;

    const float* wwarp = &wsm[w * 3 * 256];

    #pragma unroll 1
    for (int ks = 0; ks < 16; ks++) {
        CP_WAIT1();            // chunk ks resident in stage ks%3
        __syncwarp();

        const float* wstage = wwarp + (ks % 3) * 256;

        #pragma unroll
        for (int q = 0; q < 2; q++) {
            const int i0 = ks * 8 + q * 4;
            ulonglong2 xq[4];
            #pragma unroll
            for (int bi = 0; bi < 4; bi++)
                xq[bi] = *(const ulonglong2*)(xs + (bg * 4 + bi) * 132 + i0);
            #pragma unroll
            for (int r = 0; r < 8; r++) {
                const int slot = ((cq << 4) | (r * 2 + q)) ^ cq;   // phys slot
                ulonglong2 wq = *(const ulonglong2*)(wstage + slot * 4);
                #pragma unroll
                for (int bi = 0; bi < 4; bi++) {
                    ffma2(acc[bi][r], xq[bi].x, wq.x);
                    ffma2(acc[bi][r], xq[bi].y, wq.y);
                }
            }
        }

        // refill the stage consumed at iteration ks-1 with chunk ks+2
        if (ks + 2 < 16) {
            const int st = (ks + 2) % 3;
            cp16(d0 + st * 1024, wrow + (ks + 2) * 8);
            cp16(d1 + st * 1024, wrow + (ks + 2) * 8 + 4);
        }
        CP_COMMIT();           // commit every iteration (possibly empty group)
    }

    // epilogue: horizontal add of packed pairs, vectorized store
    #pragma unroll
    for (int bi = 0; bi < 4; bi++) {
        const int b = bg * 4 + bi;
        float o[8];
        #pragma unroll
        for (int r = 0; r < 8; r++) {
            float2 f = upk(acc[bi][r]);
            o[r] = f.x + f.y;
        }
        float* op = g_uhat + ((size_t)b * NIN + n) * CD + cdBase + cg * 8;
        *(float4*)(op)     = make_float4(o[0], o[1], o[2], o[3]);
        *(float4*)(op + 4) = make_float4(o[4], o[5], o[6], o[7]);
    }
}

// ---------------- Kernel 1b: iteration-0 weighted sum -----------------------
// With b_ij = 0, c collapses to exactly 1/1024 for every (n, class), so
// s0[b,c,d] = sum_n u_hat / 1024. Pure streaming reduction, no softmax pass.
// grid = (CD/256 = 5, BATCH, 8 n-segments), block = 256.
__global__ __launch_bounds__(256)
void k_sum0() {
    const int cd = blockIdx.x * 256 + threadIdx.x;
    const int b  = blockIdx.y;
    const int n0 = blockIdx.z * 128;

    const float* p = g_uhat + ((size_t)b * NIN + n0) * CD + cd;
    float s0 = 0.f, s1 = 0.f, s2 = 0.f, s3 = 0.f;
    #pragma unroll 4
    for (int k = 0; k < 128; k += 4) {
        s0 += p[(size_t)(k + 0) * CD];
        s1 += p[(size_t)(k + 1) * CD];
        s2 += p[(size_t)(k + 2) * CD];
        s3 += p[(size_t)(k + 3) * CD];
    }
    atomicAdd(&g_spart[b * CD + cd], (s0 + s1) + (s2 + s3));

    if (blockIdx.x == 0 && blockIdx.z == 0 && threadIdx.x < NC)
        g_wsum[b * NC + threadIdx.x] = 1024.0f;
}

// ---------------- Kernel 2: fused routing pass (iters 1,2) -------------------
__global__ __launch_bounds__(256)
void k_route(int iter) {
    __shared__ float v_s[CD];
    __shared__ float vn2_s[NC];
    __shared__ float sbuf[8][CD];
    __shared__ float wbuf[8][NC];

    const int b  = blockIdx.y;
    const int n0 = blockIdx.x * 32;
    const int t    = threadIdx.x;
    const int w    = t >> 5;
    const int lane = t & 31;

    for (int e = t; e < CD; e += 256) v_s[e] = g_v[b * CD + e];
    if (t < NC) vn2_s[t] = g_vn2[b * NC + t];
    __syncthreads();

    float2 sacc[NC];
    #pragma unroll
    for (int j = 0; j < NC; j++) sacc[j] = make_float2(0.f, 0.f);
    float cwacc = 0.f;

    for (int k = 0; k < 4; k++) {
        const int n = n0 + k * 8 + w;
        const float* up = g_uhat + ((size_t)b * NIN + n) * CD;

        float2 ur[NC];
        float myun2 = 0.f, mydot = 0.f;

        #pragma unroll
        for (int j = 0; j < NC; j++) {
            float2 u2 = *(const float2*)(up + j * DIM + 2 * lane);
            ur[j] = u2;
            float2 v2 = *(const float2*)(v_s + j * DIM + 2 * lane);
            float p = u2.x * u2.x + u2.y * u2.y;
            float q = u2.x * v2.x + u2.y * v2.y;
            #pragma unroll
            for (int off = 16; off > 0; off >>= 1) {
                p += __shfl_xor_sync(0xffffffffu, p, off);
                q += __shfl_xor_sync(0xffffffffu, q, off);
            }
            if (lane == j) { myun2 = p; mydot = q; }
        }

        float bnew = -3.0e38f;
        if (lane < NC) {
            float un2 = myun2;
            float a   = sqrtf(un2) / (0.5f + un2);          // squash scale of u_hat
            float dd  = 1.0f - (a * a * un2 - 2.0f * a * mydot + vn2_s[lane]);
            if (iter == 1) {
                bnew = dd;                                    // b was 0
                g_bij[(b * NIN + n) * NC + lane] = dd;
            } else {
                bnew = g_bij[(b * NIN + n) * NC + lane] + dd; // last iter: no store needed
            }
        }
        float m = bnew;
        #pragma unroll
        for (int off = 16; off > 0; off >>= 1)
            m = fmaxf(m, __shfl_xor_sync(0xffffffffu, m, off));
        float e = (lane < NC) ? __expf(bnew - m) : 0.0f;
        float ssum = e;
        #pragma unroll
        for (int off = 16; off > 0; off >>= 1)
            ssum += __shfl_xor_sync(0xffffffffu, ssum, off);
        float craw = e / ssum;

        // accumulate weighted sums (u_hat reused from registers)
        #pragma unroll
        for (int j = 0; j < NC; j++) {
            float cj = __shfl_sync(0xffffffffu, craw, j);
            sacc[j].x += cj * ur[j].x;
            sacc[j].y += cj * ur[j].y;
        }
        if (lane < NC) cwacc += craw;
    }

    // stage per-warp partials, block-reduce, one atomic per element per block
    #pragma unroll
    for (int j = 0; j < NC; j++)
        *(float2*)&sbuf[w][j * DIM + 2 * lane] = sacc[j];
    if (lane < NC) wbuf[w][lane] = cwacc;
    __syncthreads();

    for (int e = t; e < CD; e += 256) {
        float s = 0.f;
        #pragma unroll
        for (int ww = 0; ww < 8; ww++) s += sbuf[ww][e];
        atomicAdd(&g_spart[b * CD + e], s);
    }
    if (t < NC) {
        float s = 0.f;
        #pragma unroll
        for (int ww = 0; ww < 8; ww++) s += wbuf[ww][t];
        atomicAdd(&g_wsum[b * NC + t], s);
    }
}

// ---------------- Kernel 3: squash + (final) output --------------------------
__global__ __launch_bounds__(64)
void k_squash(int final_iter, float* __restrict__ out) {
    const int bj = blockIdx.x;          // b*NC + j
    const int d  = threadIdx.x;
    const int lane = d & 31, wp = d >> 5;

    float sv = g_spart[bj * DIM + d];
    float ws = g_wsum[bj];
    float s  = sv / ws;

    float p = s * s;
    #pragma unroll
    for (int off = 16; off > 0; off >>= 1)
        p += __shfl_xor_sync(0xffffffffu, p, off);
    __shared__ float red[2];
    if (lane == 0) red[wp] = p;
    __syncthreads();
    float s2 = red[0] + red[1];

    float sc = sqrtf(s2) / (0.5f + s2);
    float v  = sc * s;

    g_v[bj * DIM + d] = v;
    if (d == 0) g_vn2[bj] = sc * sc * s2;

    // reset partials so next iteration / next graph replay starts clean
    g_spart[bj * DIM + d] = 0.0f;
    if (d == 0) g_wsum[bj] = 0.0f;

    if (final_iter) {
        out[bj * DIM + d] = v;                                  // poses [B,C,D,1] flattened
        if (d == 0)
            out[BATCH * NC * DIM + bj] = sqrtf(sc * sc * s2);   // activations [B,C,1]
    }
}

// ---------------- launch -----------------------------------------------------
extern "C" void kernel_launch(void* const* d_in, const int* in_sizes, int n_in,
                              void* d_out, int out_size) {
    const float* x  = (const float*)d_in[0];
    const float* w1 = (const float*)d_in[1];
    if (n_in >= 2 && in_sizes[0] > in_sizes[1]) {   // defensive: x is the smaller input
        x  = (const float*)d_in[1];
        w1 = (const float*)d_in[0];
    }
    float* out = (float*)d_out;

    k_gemm<<<dim3(CD / 256, NIN), 256>>>(x, w1);

    k_sum0<<<dim3(CD / 256, BATCH, 8), 256>>>();
    k_squash<<<BATCH * NC, 64>>>(0, out);

    k_route<<<dim3(NIN / 32, BATCH), 256>>>(1);
    k_squash<<<BATCH * NC, 64>>>(0, out);

    k_route<<<dim3(NIN / 32, BATCH), 256>>>(2);
    k_squash<<<BATCH * NC, 64>>>(1, out);
}

// round 10
// speedup vs baseline: 1.4412x; 1.1776x over previous
#include <cuda_runtime.h>
#include <math.h>
#include <stdint.h>

#define BATCH 32
#define NIN   1024
#define NC    20
#define DIM   64
#define CD    (NC*DIM)   // 1280
#define CIN   128

// ---------------- scratch (device globals: no allocations allowed) ----------
__device__ float g_uhat[(size_t)BATCH * NIN * CD];   // 167.8 MB
__device__ float g_bij[BATCH * NIN * NC];            // routing logits
__device__ float g_spart[BATCH * NC * DIM];          // partial weighted sums (zeroed by squash)
__device__ float g_wsum[BATCH * NC];                 // partial weight sums
__device__ float g_v[BATCH * NC * DIM];              // v per iteration
__device__ float g_vn2[BATCH * NC];                  // |v|^2 per (b,class)

// ---------------- packed f32x2 helpers --------------------------------------
__device__ __forceinline__ void ffma2(unsigned long long &d,
                                      unsigned long long a,
                                      unsigned long long b) {
    asm("fma.rn.f32x2 %0, %1, %2, %0;" : "+l"(d) : "l"(a), "l"(b));
}
__device__ __forceinline__ float2 upk(unsigned long long v) {
    float2 f;
    asm("mov.b64 {%0, %1}, %2;" : "=f"(f.x), "=f"(f.y) : "l"(v));
    return f;
}
__device__ __forceinline__ void cp16(uint32_t dst, const float* src) {
    asm volatile("cp.async.cg.shared.global [%0], [%1], 16;\n"
                 :: "r"(dst), "l"(src));
}
#define CP_COMMIT() asm volatile("cp.async.commit_group;\n" ::: "memory")
#define CP_WAIT1()  asm volatile("cp.async.wait_group 1;\n" ::: "memory")

// ---------------- Kernel 1: u_hat GEMM (cp.async, leading refill) -----------
// grid = (CD/256 = 5, NIN), block = 256 (8 warps).
// Block: one n, all 32 b, 256 consecutive cd rows. Warp w owns rows
// [w*32, w*32+32). Thread tile: 4 b x 8 cd with b = bi*8 + bg (bg = t&7):
// bg stride-1 in b makes the per-warp xq LDS.128 addresses land on 8 distinct
// bank quads (row pitch 132 floats: bg*528 B, 528 mod 128 = 16) -> conflict-free.
// w streamed via cp.async.cg into a 3-stage, 1KB/stage warp-private smem ring;
// the refill for chunk ks+2 is issued right AFTER the wait for chunk ks, so
// two chunks (2 KB/warp, 32 KB/SM at 16 warps) are in flight during compute.
__global__ __launch_bounds__(256, 2)
void k_gemm(const float* __restrict__ x, const float* __restrict__ w1) {
    __shared__ __align__(16) float xs[32 * 132];        // padded x tile (16.9 KB)
    __shared__ __align__(16) float wsm[8 * 3 * 256];    // 8 warps x 3 stages x 1KB

    const int n      = blockIdx.y;
    const int cdBase = blockIdx.x * 256;
    const int t      = threadIdx.x;
    const int w      = t >> 5;
    const int lane   = t & 31;

    // stage x[:, n, :]  (32 x 128) into smem, coalesced
    for (int e = t; e < 32 * 128; e += 256) {
        int bb = e >> 7, i = e & 127;
        xs[bb * 132 + i] = x[((size_t)bb * NIN + n) * CIN + i];
    }
    __syncthreads();

    // producer: lane handles w row cd = cdBase + w*32 + lane; two 16B pieces
    // per chunk at logical slots 2*lane, 2*lane+1, phys slot = s ^ (s>>4).
    const float* wrow = w1 + ((size_t)n * CD + cdBase + w * 32 + lane) * CIN;
    uint32_t wb = (uint32_t)__cvta_generic_to_shared(&wsm[w * 3 * 256]);
    const uint32_t d0 = wb + (uint32_t)(((2 * lane)     ^ (lane >> 3)) << 4);
    const uint32_t d1 = wb + (uint32_t)(((2 * lane + 1) ^ (lane >> 3)) << 4);

    // prologue: chunks 0,1 in flight
    cp16(d0,        wrow + 0);  cp16(d1,        wrow + 4);  CP_COMMIT();
    cp16(d0 + 1024, wrow + 8);  cp16(d1 + 1024, wrow + 12); CP_COMMIT();

    const int bg = t & 7;
    const int cg = t >> 3;
    const int cq = cg & 3;

    unsigned long long acc[4][8];
    #pragma unroll
    for (int bi = 0; bi < 4; bi++)
        #pragma unroll
        for (int r = 0; r < 8; r++) acc[bi][r] = 0ull;

    const float* wwarp = &wsm[w * 3 * 256];

    int stC = 0;   // stage holding chunk ks
    int stP = 2;   // stage to refill with chunk ks+2
    #pragma unroll 1
    for (int ks = 0; ks < 16; ks++) {
        CP_WAIT1();            // chunk ks resident in stage stC
        __syncwarp();

        // leading refill: chunk ks+2 into the stage consumed at iter ks-1
        if (ks + 2 < 16) {
            cp16(d0 + stP * 1024, wrow + (ks + 2) * 8);
            cp16(d1 + stP * 1024, wrow + (ks + 2) * 8 + 4);
        }
        CP_COMMIT();           // one group per iteration (possibly empty)

        const float* wstage = wwarp + stC * 256;

        #pragma unroll
        for (int q = 0; q < 2; q++) {
            const int i0 = ks * 8 + q * 4;
            ulonglong2 xq[4];
            #pragma unroll
            for (int bi = 0; bi < 4; bi++)
                xq[bi] = *(const ulonglong2*)(xs + (bi * 8 + bg) * 132 + i0);
            #pragma unroll
            for (int r = 0; r < 8; r++) {
                const int slot = ((cq << 4) | (r * 2 + q)) ^ cq;   // phys slot
                ulonglong2 wq = *(const ulonglong2*)(wstage + slot * 4);
                #pragma unroll
                for (int bi = 0; bi < 4; bi++) {
                    ffma2(acc[bi][r], xq[bi].x, wq.x);
                    ffma2(acc[bi][r], xq[bi].y, wq.y);
                }
            }
        }

        stC = (stC == 2) ? 0 : stC + 1;
        stP = (stP == 2) ? 0 : stP + 1;
    }

    // epilogue: horizontal add of packed pairs, vectorized store (b = bi*8+bg)
    #pragma unroll
    for (int bi = 0; bi < 4; bi++) {
        const int b = bi * 8 + bg;
        float o[8];
        #pragma unroll
        for (int r = 0; r < 8; r++) {
            float2 f = upk(acc[bi][r]);
            o[r] = f.x + f.y;
        }
        float* op = g_uhat + ((size_t)b * NIN + n) * CD + cdBase + cg * 8;
        *(float4*)(op)     = make_float4(o[0], o[1], o[2], o[3]);
        *(float4*)(op + 4) = make_float4(o[4], o[5], o[6], o[7]);
    }
}

// ---------------- Kernel 1b: iteration-0 weighted sum -----------------------
// With b_ij = 0, c collapses to exactly 1/1024 for every (n, class), so
// s0[b,c,d] = sum_n u_hat / 1024. Pure streaming reduction, no softmax pass.
// grid = (CD/256 = 5, BATCH, 8 n-segments), block = 256.
__global__ __launch_bounds__(256)
void k_sum0() {
    const int cd = blockIdx.x * 256 + threadIdx.x;
    const int b  = blockIdx.y;
    const int n0 = blockIdx.z * 128;

    const float* p = g_uhat + ((size_t)b * NIN + n0) * CD + cd;
    float s0 = 0.f, s1 = 0.f, s2 = 0.f, s3 = 0.f;
    #pragma unroll 4
    for (int k = 0; k < 128; k += 4) {
        s0 += p[(size_t)(k + 0) * CD];
        s1 += p[(size_t)(k + 1) * CD];
        s2 += p[(size_t)(k + 2) * CD];
        s3 += p[(size_t)(k + 3) * CD];
    }
    atomicAdd(&g_spart[b * CD + cd], (s0 + s1) + (s2 + s3));

    if (blockIdx.x == 0 && blockIdx.z == 0 && threadIdx.x < NC)
        g_wsum[b * NC + threadIdx.x] = 1024.0f;
}

// ---------------- Kernel 2: fused routing pass (iters 1,2) -------------------
__global__ __launch_bounds__(256)
void k_route(int iter) {
    __shared__ float v_s[CD];
    __shared__ float vn2_s[NC];
    __shared__ float sbuf[8][CD];
    __shared__ float wbuf[8][NC];

    const int b  = blockIdx.y;
    const int n0 = blockIdx.x * 32;
    const int t    = threadIdx.x;
    const int w    = t >> 5;
    const int lane = t & 31;

    for (int e = t; e < CD; e += 256) v_s[e] = g_v[b * CD + e];
    if (t < NC) vn2_s[t] = g_vn2[b * NC + t];
    __syncthreads();

    float2 sacc[NC];
    #pragma unroll
    for (int j = 0; j < NC; j++) sacc[j] = make_float2(0.f, 0.f);
    float cwacc = 0.f;

    for (int k = 0; k < 4; k++) {
        const int n = n0 + k * 8 + w;
        const float* up = g_uhat + ((size_t)b * NIN + n) * CD;

        float2 ur[NC];
        float myun2 = 0.f, mydot = 0.f;

        #pragma unroll
        for (int j = 0; j < NC; j++) {
            float2 u2 = *(const float2*)(up + j * DIM + 2 * lane);
            ur[j] = u2;
            float2 v2 = *(const float2*)(v_s + j * DIM + 2 * lane);
            float p = u2.x * u2.x + u2.y * u2.y;
            float q = u2.x * v2.x + u2.y * v2.y;
            #pragma unroll
            for (int off = 16; off > 0; off >>= 1) {
                p += __shfl_xor_sync(0xffffffffu, p, off);
                q += __shfl_xor_sync(0xffffffffu, q, off);
            }
            if (lane == j) { myun2 = p; mydot = q; }
        }

        float bnew = -3.0e38f;
        if (lane < NC) {
            float un2 = myun2;
            float a   = sqrtf(un2) / (0.5f + un2);          // squash scale of u_hat
            float dd  = 1.0f - (a * a * un2 - 2.0f * a * mydot + vn2_s[lane]);
            if (iter == 1) {
                bnew = dd;                                    // b was 0
                g_bij[(b * NIN + n) * NC + lane] = dd;
            } else {
                bnew = g_bij[(b * NIN + n) * NC + lane] + dd; // last iter: no store needed
            }
        }
        float m = bnew;
        #pragma unroll
        for (int off = 16; off > 0; off >>= 1)
            m = fmaxf(m, __shfl_xor_sync(0xffffffffu, m, off));
        float e = (lane < NC) ? __expf(bnew - m) : 0.0f;
        float ssum = e;
        #pragma unroll
        for (int off = 16; off > 0; off >>= 1)
            ssum += __shfl_xor_sync(0xffffffffu, ssum, off);
        float craw = e / ssum;

        // accumulate weighted sums (u_hat reused from registers)
        #pragma unroll
        for (int j = 0; j < NC; j++) {
            float cj = __shfl_sync(0xffffffffu, craw, j);
            sacc[j].x += cj * ur[j].x;
            sacc[j].y += cj * ur[j].y;
        }
        if (lane < NC) cwacc += craw;
    }

    // stage per-warp partials, block-reduce, one atomic per element per block
    #pragma unroll
    for (int j = 0; j < NC; j++)
        *(float2*)&sbuf[w][j * DIM + 2 * lane] = sacc[j];
    if (lane < NC) wbuf[w][lane] = cwacc;
    __syncthreads();

    for (int e = t; e < CD; e += 256) {
        float s = 0.f;
        #pragma unroll
        for (int ww = 0; ww < 8; ww++) s += sbuf[ww][e];
        atomicAdd(&g_spart[b * CD + e], s);
    }
    if (t < NC) {
        float s = 0.f;
        #pragma unroll
        for (int ww = 0; ww < 8; ww++) s += wbuf[ww][t];
        atomicAdd(&g_wsum[b * NC + t], s);
    }
}

// ---------------- Kernel 3: squash + (final) output --------------------------
__global__ __launch_bounds__(64)
void k_squash(int final_iter, float* __restrict__ out) {
    const int bj = blockIdx.x;          // b*NC + j
    const int d  = threadIdx.x;
    const int lane = d & 31, wp = d >> 5;

    float sv = g_spart[bj * DIM + d];
    float ws = g_wsum[bj];
    float s  = sv / ws;

    float p = s * s;
    #pragma unroll
    for (int off = 16; off > 0; off >>= 1)
        p += __shfl_xor_sync(0xffffffffu, p, off);
    __shared__ float red[2];
    if (lane == 0) red[wp] = p;
    __syncthreads();
    float s2 = red[0] + red[1];

    float sc = sqrtf(s2) / (0.5f + s2);
    float v  = sc * s;

    g_v[bj * DIM + d] = v;
    if (d == 0) g_vn2[bj] = sc * sc * s2;

    // reset partials so next iteration / next graph replay starts clean
    g_spart[bj * DIM + d] = 0.0f;
    if (d == 0) g_wsum[bj] = 0.0f;

    if (final_iter) {
        out[bj * DIM + d] = v;                                  // poses [B,C,D,1] flattened
        if (d == 0)
            out[BATCH * NC * DIM + bj] = sqrtf(sc * sc * s2);   // activations [B,C,1]
    }
}

// ---------------- launch -----------------------------------------------------
extern "C" void kernel_launch(void* const* d_in, const int* in_sizes, int n_in,
                              void* d_out, int out_size) {
    const float* x  = (const float*)d_in[0];
    const float* w1 = (const float*)d_in[1];
    if (n_in >= 2 && in_sizes[0] > in_sizes[1]) {   // defensive: x is the smaller input
        x  = (const float*)d_in[1];
        w1 = (const float*)d_in[0];
    }
    float* out = (float*)d_out;

    k_gemm<<<dim3(CD / 256, NIN), 256>>>(x, w1);

    k_sum0<<<dim3(CD / 256, BATCH, 8), 256>>>();
    k_squash<<<BATCH * NC, 64>>>(0, out);

    k_route<<<dim3(NIN / 32, BATCH), 256>>>(1);
    k_squash<<<BATCH * NC, 64>>>(0, out);

    k_route<<<dim3(NIN / 32, BATCH), 256>>>(2);
    k_squash<<<BATCH * NC, 64>>>(1, out);
}

// round 11
// speedup vs baseline: 1.5574x; 1.0806x over previous
#include <cuda_runtime.h>
#include <math.h>
#include <stdint.h>

#define BATCH 32
#define NIN   1024
#define NC    20
#define DIM   64
#define CD    (NC*DIM)   // 1280
#define CIN   128

// ---------------- scratch (device globals: no allocations allowed) ----------
__device__ float g_uhat[(size_t)BATCH * NIN * CD];   // 167.8 MB
__device__ float g_bij[BATCH * NIN * NC];            // routing logits
__device__ float g_spart[BATCH * NC * DIM];          // partial weighted sums (zeroed by squash)
__device__ float g_wsum[BATCH * NC];                 // partial weight sums
__device__ float g_v[BATCH * NC * DIM];              // v per iteration
__device__ float g_vn2[BATCH * NC];                  // |v|^2 per (b,class)

// ---------------- packed f32x2 helpers --------------------------------------
__device__ __forceinline__ void ffma2(unsigned long long &d,
                                      unsigned long long a,
                                      unsigned long long b) {
    asm("fma.rn.f32x2 %0, %1, %2, %0;" : "+l"(d) : "l"(a), "l"(b));
}
__device__ __forceinline__ float2 upk(unsigned long long v) {
    float2 f;
    asm("mov.b64 {%0, %1}, %2;" : "=f"(f.x), "=f"(f.y) : "l"(v));
    return f;
}
__device__ __forceinline__ void cp16(uint32_t dst, const float* src) {
    asm volatile("cp.async.cg.shared.global [%0], [%1], 16;\n"
                 :: "r"(dst), "l"(src));
}
#define CP_COMMIT() asm volatile("cp.async.commit_group;\n" ::: "memory")
#define CP_WAIT1()  asm volatile("cp.async.wait_group 1;\n" ::: "memory")

// ---------------- Kernel 1: u_hat GEMM (cp.async, paired-lane producer) -----
// grid = (CD/256 = 5, NIN), block = 256 (8 warps).
// Block: one n, all 32 b, 256 consecutive cd rows. Warp w owns rows
// [w*32, w*32+32). Thread tile: 4 b x 8 cd with b = bi*8 + bg (bg = t&7):
// conflict-free xq LDS (row pitch 132 floats).
// Producer: w streamed via cp.async.cg into a 3-stage 1KB/stage warp-private
// smem ring. Lanes are PAIRED: lane -> (row = lane>>1, half = lane&1), so
// instruction A covers rows 0..15 with both 16B halves of each 32B row-piece
// in ONE instruction (16 distinct 128B lines -> 16 L1tex wavefronts), and
// instruction B covers rows 16..31. This halves wavefront pressure vs the
// d0/d1-per-lane split (which charged every line twice). Logical smem slot
// s = row*2 + half, phys = s ^ (s>>4) -- identical consumer layout.
__global__ __launch_bounds__(256, 2)
void k_gemm(const float* __restrict__ x, const float* __restrict__ w1) {
    __shared__ __align__(16) float xs[32 * 132];        // padded x tile (16.9 KB)
    __shared__ __align__(16) float wsm[8 * 3 * 256];    // 8 warps x 3 stages x 1KB

    const int n      = blockIdx.y;
    const int cdBase = blockIdx.x * 256;
    const int t      = threadIdx.x;
    const int w      = t >> 5;
    const int lane   = t & 31;

    // stage x[:, n, :]  (32 x 128) into smem, coalesced
    for (int e = t; e < 32 * 128; e += 256) {
        int bb = e >> 7, i = e & 127;
        xs[bb * 132 + i] = x[((size_t)bb * NIN + n) * CIN + i];
    }
    __syncthreads();

    // paired-lane producer mapping
    const int rowp = lane >> 1;           // 0..15
    const int half = lane & 1;            // 16B half within the 32B row piece
    const float* wA = w1 + ((size_t)n * CD + cdBase + w * 32 + rowp) * CIN + half * 4;
    const float* wB = wA + 16 * CIN;      // rows 16..31
    uint32_t wb = (uint32_t)__cvta_generic_to_shared(&wsm[w * 3 * 256]);
    const uint32_t sA = (uint32_t)(rowp * 2 + half);        // 0..31
    const uint32_t sB = sA + 32;                            // 32..63
    const uint32_t dA = wb + ((sA ^ (sA >> 4)) << 4);
    const uint32_t dB = wb + ((sB ^ (sB >> 4)) << 4);

    // prologue: chunks 0,1 in flight
    cp16(dA,        wA + 0);  cp16(dB,        wB + 0);  CP_COMMIT();
    cp16(dA + 1024, wA + 8);  cp16(dB + 1024, wB + 8);  CP_COMMIT();

    const int bg = t & 7;
    const int cg = t >> 3;
    const int cq = cg & 3;

    unsigned long long acc[4][8];
    #pragma unroll
    for (int bi = 0; bi < 4; bi++)
        #pragma unroll
        for (int r = 0; r < 8; r++) acc[bi][r] = 0ull;

    const float* wwarp = &wsm[w * 3 * 256];

    int stC = 0;   // stage holding chunk ks
    int stP = 2;   // stage to refill with chunk ks+2
    #pragma unroll 1
    for (int ks = 0; ks < 16; ks++) {
        CP_WAIT1();            // chunk ks resident in stage stC
        __syncwarp();

        // leading refill: chunk ks+2 into the stage consumed at iter ks-1
        if (ks + 2 < 16) {
            cp16(dA + stP * 1024, wA + (ks + 2) * 8);
            cp16(dB + stP * 1024, wB + (ks + 2) * 8);
        }
        CP_COMMIT();           // one group per iteration (possibly empty)

        const float* wstage = wwarp + stC * 256;

        #pragma unroll
        for (int q = 0; q < 2; q++) {
            const int i0 = ks * 8 + q * 4;
            ulonglong2 xq[4];
            #pragma unroll
            for (int bi = 0; bi < 4; bi++)
                xq[bi] = *(const ulonglong2*)(xs + (bi * 8 + bg) * 132 + i0);
            #pragma unroll
            for (int r = 0; r < 8; r++) {
                const int slot = ((cq << 4) | (r * 2 + q)) ^ cq;   // phys slot
                ulonglong2 wq = *(const ulonglong2*)(wstage + slot * 4);
                #pragma unroll
                for (int bi = 0; bi < 4; bi++) {
                    ffma2(acc[bi][r], xq[bi].x, wq.x);
                    ffma2(acc[bi][r], xq[bi].y, wq.y);
                }
            }
        }

        stC = (stC == 2) ? 0 : stC + 1;
        stP = (stP == 2) ? 0 : stP + 1;
    }

    // epilogue: horizontal add of packed pairs, vectorized store (b = bi*8+bg)
    #pragma unroll
    for (int bi = 0; bi < 4; bi++) {
        const int b = bi * 8 + bg;
        float o[8];
        #pragma unroll
        for (int r = 0; r < 8; r++) {
            float2 f = upk(acc[bi][r]);
            o[r] = f.x + f.y;
        }
        float* op = g_uhat + ((size_t)b * NIN + n) * CD + cdBase + cg * 8;
        *(float4*)(op)     = make_float4(o[0], o[1], o[2], o[3]);
        *(float4*)(op + 4) = make_float4(o[4], o[5], o[6], o[7]);
    }
}

// ---------------- Kernel 1b: iteration-0 weighted sum -----------------------
// With b_ij = 0, c collapses to exactly 1/1024 for every (n, class), so
// s0[b,c,d] = sum_n u_hat / 1024. Pure streaming reduction, no softmax pass.
// grid = (CD/256 = 5, BATCH, 8 n-segments), block = 256.
__global__ __launch_bounds__(256)
void k_sum0() {
    const int cd = blockIdx.x * 256 + threadIdx.x;
    const int b  = blockIdx.y;
    const int n0 = blockIdx.z * 128;

    const float* p = g_uhat + ((size_t)b * NIN + n0) * CD + cd;
    float s0 = 0.f, s1 = 0.f, s2 = 0.f, s3 = 0.f;
    #pragma unroll 4
    for (int k = 0; k < 128; k += 4) {
        s0 += p[(size_t)(k + 0) * CD];
        s1 += p[(size_t)(k + 1) * CD];
        s2 += p[(size_t)(k + 2) * CD];
        s3 += p[(size_t)(k + 3) * CD];
    }
    atomicAdd(&g_spart[b * CD + cd], (s0 + s1) + (s2 + s3));

    if (blockIdx.x == 0 && blockIdx.z == 0 && threadIdx.x < NC)
        g_wsum[b * NC + threadIdx.x] = 1024.0f;
}

// ---------------- Kernel 2: fused routing pass (iters 1,2) -------------------
__global__ __launch_bounds__(256)
void k_route(int iter) {
    __shared__ float v_s[CD];
    __shared__ float vn2_s[NC];
    __shared__ float sbuf[8][CD];
    __shared__ float wbuf[8][NC];

    const int b  = blockIdx.y;
    const int n0 = blockIdx.x * 32;
    const int t    = threadIdx.x;
    const int w    = t >> 5;
    const int lane = t & 31;

    for (int e = t; e < CD; e += 256) v_s[e] = g_v[b * CD + e];
    if (t < NC) vn2_s[t] = g_vn2[b * NC + t];
    __syncthreads();

    float2 sacc[NC];
    #pragma unroll
    for (int j = 0; j < NC; j++) sacc[j] = make_float2(0.f, 0.f);
    float cwacc = 0.f;

    for (int k = 0; k < 4; k++) {
        const int n = n0 + k * 8 + w;
        const float* up = g_uhat + ((size_t)b * NIN + n) * CD;

        float2 ur[NC];
        float myun2 = 0.f, mydot = 0.f;

        #pragma unroll
        for (int j = 0; j < NC; j++) {
            float2 u2 = *(const float2*)(up + j * DIM + 2 * lane);
            ur[j] = u2;
            float2 v2 = *(const float2*)(v_s + j * DIM + 2 * lane);
            float p = u2.x * u2.x + u2.y * u2.y;
            float q = u2.x * v2.x + u2.y * v2.y;
            #pragma unroll
            for (int off = 16; off > 0; off >>= 1) {
                p += __shfl_xor_sync(0xffffffffu, p, off);
                q += __shfl_xor_sync(0xffffffffu, q, off);
            }
            if (lane == j) { myun2 = p; mydot = q; }
        }

        float bnew = -3.0e38f;
        if (lane < NC) {
            float un2 = myun2;
            float a   = sqrtf(un2) / (0.5f + un2);          // squash scale of u_hat
            float dd  = 1.0f - (a * a * un2 - 2.0f * a * mydot + vn2_s[lane]);
            if (iter == 1) {
                bnew = dd;                                    // b was 0
                g_bij[(b * NIN + n) * NC + lane] = dd;
            } else {
                bnew = g_bij[(b * NIN + n) * NC + lane] + dd; // last iter: no store needed
            }
        }
        float m = bnew;
        #pragma unroll
        for (int off = 16; off > 0; off >>= 1)
            m = fmaxf(m, __shfl_xor_sync(0xffffffffu, m, off));
        float e = (lane < NC) ? __expf(bnew - m) : 0.0f;
        float ssum = e;
        #pragma unroll
        for (int off = 16; off > 0; off >>= 1)
            ssum += __shfl_xor_sync(0xffffffffu, ssum, off);
        float craw = e / ssum;

        // accumulate weighted sums (u_hat reused from registers)
        #pragma unroll
        for (int j = 0; j < NC; j++) {
            float cj = __shfl_sync(0xffffffffu, craw, j);
            sacc[j].x += cj * ur[j].x;
            sacc[j].y += cj * ur[j].y;
        }
        if (lane < NC) cwacc += craw;
    }

    // stage per-warp partials, block-reduce, one atomic per element per block
    #pragma unroll
    for (int j = 0; j < NC; j++)
        *(float2*)&sbuf[w][j * DIM + 2 * lane] = sacc[j];
    if (lane < NC) wbuf[w][lane] = cwacc;
    __syncthreads();

    for (int e = t; e < CD; e += 256) {
        float s = 0.f;
        #pragma unroll
        for (int ww = 0; ww < 8; ww++) s += sbuf[ww][e];
        atomicAdd(&g_spart[b * CD + e], s);
    }
    if (t < NC) {
        float s = 0.f;
        #pragma unroll
        for (int ww = 0; ww < 8; ww++) s += wbuf[ww][t];
        atomicAdd(&g_wsum[b * NC + t], s);
    }
}

// ---------------- Kernel 3: squash + (final) output --------------------------
__global__ __launch_bounds__(64)
void k_squash(int final_iter, float* __restrict__ out) {
    const int bj = blockIdx.x;          // b*NC + j
    const int d  = threadIdx.x;
    const int lane = d & 31, wp = d >> 5;

    float sv = g_spart[bj * DIM + d];
    float ws = g_wsum[bj];
    float s  = sv / ws;

    float p = s * s;
    #pragma unroll
    for (int off = 16; off > 0; off >>= 1)
        p += __shfl_xor_sync(0xffffffffu, p, off);
    __shared__ float red[2];
    if (lane == 0) red[wp] = p;
    __syncthreads();
    float s2 = red[0] + red[1];

    float sc = sqrtf(s2) / (0.5f + s2);
    float v  = sc * s;

    g_v[bj * DIM + d] = v;
    if (d == 0) g_vn2[bj] = sc * sc * s2;

    // reset partials so next iteration / next graph replay starts clean
    g_spart[bj * DIM + d] = 0.0f;
    if (d == 0) g_wsum[bj] = 0.0f;

    if (final_iter) {
        out[bj * DIM + d] = v;                                  // poses [B,C,D,1] flattened
        if (d == 0)
            out[BATCH * NC * DIM + bj] = sqrtf(sc * sc * s2);   // activations [B,C,1]
    }
}

// ---------------- launch -----------------------------------------------------
extern "C" void kernel_launch(void* const* d_in, const int* in_sizes, int n_in,
                              void* d_out, int out_size) {
    const float* x  = (const float*)d_in[0];
    const float* w1 = (const float*)d_in[1];
    if (n_in >= 2 && in_sizes[0] > in_sizes[1]) {   // defensive: x is the smaller input
        x  = (const float*)d_in[1];
        w1 = (const float*)d_in[0];
    }
    float* out = (float*)d_out;

    k_gemm<<<dim3(CD / 256, NIN), 256>>>(x, w1);

    k_sum0<<<dim3(CD / 256, BATCH, 8), 256>>>();
    k_squash<<<BATCH * NC, 64>>>(0, out);

    k_route<<<dim3(NIN / 32, BATCH), 256>>>(1);
    k_squash<<<BATCH * NC, 64>>>(0, out);

    k_route<<<dim3(NIN / 32, BATCH), 256>>>(2);
    k_squash<<<BATCH * NC, 64>>>(1, out);
}